// round 11
// baseline (speedup 1.0000x reference)
#include <cuda_runtime.h>

#define NVOCAB 50001   // VOCAB + 1 rows
#define EMB    32
#define UNITS  16
#define BATCH  256
#define TLEN   4096
#define GATE3  48
#define PD     8       // prefetch depth (steps)

// Precomputed emb_table @ kernel + bias[0]  : [NVOCAB, 48]
__device__ float g_table2[NVOCAB * GATE3];

__device__ __forceinline__ float sigf(float x) {
    return __fdividef(1.0f, 1.0f + __expf(-x));
}

// ---------------------------------------------------------------------------
// Kernel A: g_table2[v][j] = sum_e emb[v][e] * kernel[e][j] + bias0[j]
// One warp per vocab row (strided). lane j -> col j; lanes 0-15 also col 32+j.
// ---------------------------------------------------------------------------
__global__ __launch_bounds__(128) void build_table(
    const float* __restrict__ emb,
    const float* __restrict__ kern,
    const float* __restrict__ bias)
{
    const int lane = threadIdx.x & 31;
    const int l2   = lane & 15;
    const int w    = (blockIdx.x * blockDim.x + threadIdx.x) >> 5;
    const int nw   = (gridDim.x * blockDim.x) >> 5;

    float KA[EMB], KB[EMB];
#pragma unroll
    for (int e = 0; e < EMB; e++) {
        KA[e] = kern[e * GATE3 + lane];
        KB[e] = kern[e * GATE3 + 32 + l2];
    }
    const float bA = bias[lane];
    const float bB = bias[32 + l2];

    for (int v = w; v < NVOCAB; v += nw) {
        float ev = emb[(long)v * EMB + lane];   // coalesced 128B
        float a = bA, b = bB;
#pragma unroll
        for (int e = 0; e < EMB; e++) {
            float s = __shfl_sync(0xffffffffu, ev, e);
            a = fmaf(s, KA[e], a);
            b = fmaf(s, KB[e], b);
        }
        g_table2[(long)v * GATE3 + lane] = a;
        if (lane < 16) g_table2[(long)v * GATE3 + 32 + lane] = b;
    }
}

// ---------------------------------------------------------------------------
// Kernel B: GRU scan. One batch per warp; 2 warps per CTA (one per SMSP 0/1).
// Column mapping per lane l:
//   c1 = l ^ 16  -> lanes 0-15 compute the r-column, lanes 16-31 the z-column
//   lanes 0-15 also own column 32+l (rh / candidate column)
// so both sigmoids of gate set #1 happen in one warp-wide pass and the z value
// is shuffled down while the candidate sigmoid is in flight.
// ---------------------------------------------------------------------------
__global__ __launch_bounds__(64, 1) void gru_scan(
    const int*   __restrict__ ids,
    const float* __restrict__ reck,
    const float* __restrict__ bias,
    float*       __restrict__ out)
{
    __shared__ int sid[2][TLEN];           // 32 KB: this warp's token ids

    const int lane = threadIdx.x & 31;
    const int w    = threadIdx.x >> 5;
    const int b    = blockIdx.x * 2 + w;

    // stage ids into smem (coalesced)
    const int* idp = ids + (long)b * TLEN;
    for (int k = lane; k < TLEN; k += 32) sid[w][k] = idp[k];
    __syncwarp();
    const int* sw = sid[w];

    const int c1 = lane ^ 16;
    const int l2 = lane & 15;

    // recurrent kernel columns in registers
    float R1[UNITS], R2[UNITS];
#pragma unroll
    for (int i = 0; i < UNITS; i++) {
        R1[i] = reck[i * GATE3 + c1];
        R2[i] = reck[i * GATE3 + 32 + l2];
    }
    const float b1 = bias[GATE3 + c1];        // recurrent bias, col c1
    const float b2 = bias[GATE3 + 32 + l2];   // recurrent bias, rh col

    float hv[UNITS];
#pragma unroll
    for (int i = 0; i < UNITS; i++) hv[i] = 0.0f;
    float hcur = 0.0f;                         // lane u (<16) holds h[u]

    // prefetch ring for input-projection rows (x1 = col c1, x2 = col 32+l2)
    float x1b[PD], x2b[PD];
#pragma unroll
    for (int k = 0; k < PD; k++) {
        const float* row = g_table2 + (long)sw[k] * GATE3;
        x1b[k] = row[c1];
        x2b[k] = row[32 + l2];
    }

    for (int t0 = 0; t0 < TLEN; t0 += PD) {
#pragma unroll
        for (int k = 0; k < PD; k++) {
            const float x1 = x1b[k];
            const float x2 = x2b[k];

            // refill ring PD steps ahead (off the critical path)
            int tn  = t0 + k + PD;
            int idn = sw[(tn < TLEN) ? tn : 0];
            const float* row = g_table2 + (long)idn * GATE3;
            x1b[k] = row[c1];
            x2b[k] = row[32 + l2];

            // rec matvec, 4-way split chains (fold bias + x1 into chain 0)
            const float bx = b1 + x1;
            float p0 = fmaf(hv[0],  R1[0],  fmaf(hv[4],  R1[4],
                       fmaf(hv[8],  R1[8],  fmaf(hv[12], R1[12], bx))));
            float p1 = fmaf(hv[1],  R1[1],  fmaf(hv[5],  R1[5],
                       fmaf(hv[9],  R1[9],  hv[13] * R1[13])));
            float p2 = fmaf(hv[2],  R1[2],  fmaf(hv[6],  R1[6],
                       fmaf(hv[10], R1[10], hv[14] * R1[14])));
            float p3 = fmaf(hv[3],  R1[3],  fmaf(hv[7],  R1[7],
                       fmaf(hv[11], R1[11], hv[15] * R1[15])));
            float acc1 = (p0 + p1) + (p2 + p3);   // = x1 + (h@R + b)[c1]

            float q0 = fmaf(hv[0],  R2[0],  fmaf(hv[4],  R2[4],
                       fmaf(hv[8],  R2[8],  fmaf(hv[12], R2[12], b2))));
            float q1 = fmaf(hv[1],  R2[1],  fmaf(hv[5],  R2[5],
                       fmaf(hv[9],  R2[9],  hv[13] * R2[13])));
            float q2 = fmaf(hv[2],  R2[2],  fmaf(hv[6],  R2[6],
                       fmaf(hv[10], R2[10], hv[14] * R2[14])));
            float q3 = fmaf(hv[3],  R2[3],  fmaf(hv[7],  R2[7],
                       fmaf(hv[11], R2[11], hv[15] * R2[15])));
            float acc2 = (q0 + q1) + (q2 + q3);   // = (h@R + b)[32+l2]

            // gate set 1: lanes<16 -> r, lanes>=16 -> z (same instructions)
            float g1 = sigf(acc1);
            // pull z_u down from lane u+16; overlaps the candidate sigmoid
            float z  = __shfl_down_sync(0xffffffffu, g1, 16);
            // candidate: hh = sigmoid(xh + r * rh)   (lanes<16 meaningful)
            float hh = sigf(fmaf(g1, acc2, x2));
            // h_new = z*h + (1-z)*hh
            float hn = fmaf(z, hcur - hh, hh);
            hcur = hn;

            // broadcast new state to all lanes
#pragma unroll
            for (int i = 0; i < UNITS; i++)
                hv[i] = __shfl_sync(0xffffffffu, hn, i);
        }
    }

    if (lane < 16) out[(long)b * UNITS + lane] = hcur;
}

// ---------------------------------------------------------------------------
extern "C" void kernel_launch(void* const* d_in, const int* in_sizes, int n_in,
                              void* d_out, int out_size)
{
    const int*   ids  = (const int*)  d_in[0];   // [256, 4096] int32
    const float* emb  = (const float*)d_in[1];   // [50001, 32]
    const float* kern = (const float*)d_in[2];   // [32, 48]
    const float* reck = (const float*)d_in[3];   // [16, 48]
    const float* bias = (const float*)d_in[4];   // [2, 48]
    float*       out  = (float*)d_out;           // [256, 16]

    (void)in_sizes; (void)n_in; (void)out_size;

    build_table<<<256, 128>>>(emb, kern, bias);
    gru_scan<<<BATCH / 2, 64>>>(ids, reck, bias, out);
}

// round 12
// speedup vs baseline: 1.1444x; 1.1444x over previous
#include <cuda_runtime.h>

#define NVOCAB 50001   // VOCAB + 1 rows
#define EMB    32
#define UNITS  16
#define BATCH  256
#define TLEN   4096
#define GATE3  48
#define PD     8       // prefetch depth (steps)

// Repacked, pre-scaled input projection table: [NVOCAB][64] floats.
// Row layout, for lane l (l2 = l&15, c1 = l^16):
//   pos 2l   = 0.5 * (emb@kernel + bias0)[c1]       (r-col for l<16, z-col for l>=16)
//   pos 2l+1 = 0.5 * (emb@kernel + bias0)[32 + l2]  (candidate col)
// 12.8 MB -> L2-resident after first pass.
__device__ float g_table2[(long)NVOCAB * 64];

__device__ __forceinline__ float tanh_ap(float x) {
    float y; asm("tanh.approx.f32 %0, %1;" : "=f"(y) : "f"(x)); return y;
}
__device__ __forceinline__ float ex2_ap(float x) {
    float y; asm("ex2.approx.f32 %0, %1;" : "=f"(y) : "f"(x)); return y;
}
__device__ __forceinline__ float rcp_ap(float x) {
    float y; asm("rcp.approx.f32 %0, %1;" : "=f"(y) : "f"(x)); return y;
}

// ---------------------------------------------------------------------------
// Kernel A: build the repacked table.  One warp per vocab row (strided).
// ---------------------------------------------------------------------------
__global__ __launch_bounds__(128) void build_table(
    const float* __restrict__ emb,
    const float* __restrict__ kern,
    const float* __restrict__ bias)
{
    const int lane = threadIdx.x & 31;
    const int l2   = lane & 15;
    const int c1   = lane ^ 16;
    const int w    = (blockIdx.x * blockDim.x + threadIdx.x) >> 5;
    const int nw   = (gridDim.x * blockDim.x) >> 5;

    float KA[EMB], KB[EMB];
#pragma unroll
    for (int e = 0; e < EMB; e++) {
        KA[e] = kern[e * GATE3 + c1];
        KB[e] = kern[e * GATE3 + 32 + l2];
    }
    const float bA = bias[c1];
    const float bB = bias[32 + l2];

    for (int v = w; v < NVOCAB; v += nw) {
        float ev = emb[(long)v * EMB + lane];   // coalesced 128B
        float a = bA, b = bB;
#pragma unroll
        for (int e = 0; e < EMB; e++) {
            float s = __shfl_sync(0xffffffffu, ev, e);
            a = fmaf(s, KA[e], a);
            b = fmaf(s, KB[e], b);
        }
        float2 p; p.x = 0.5f * a; p.y = 0.5f * b;
        *reinterpret_cast<float2*>(&g_table2[(long)v * 64 + 2 * lane]) = p;
    }
}

// ---------------------------------------------------------------------------
// Kernel B: GRU scan. One batch per warp; 2 warps per CTA (SMSP 0 and 1).
// Lane mapping: c1 = l^16 -> lanes 0-15 compute r-column, lanes 16-31 the
// z-column with the SAME instructions; lanes 0-15 additionally own the
// candidate column 32+l2. Everything is pre-scaled by 0.5 so the shared gate
// is  g = 0.5 + 0.5*tanh(acc)  (exact sigmoid, MUFU.TANH approx), and the
// candidate uses exact-ish ex2+rcp:  hh = 1/(1 + 2^(-2*log2e * y)).
// ---------------------------------------------------------------------------
__global__ __launch_bounds__(64, 1) void gru_scan(
    const int*   __restrict__ ids,
    const float* __restrict__ reck,
    const float* __restrict__ bias,
    float*       __restrict__ out)
{
    __shared__ int sid[2][TLEN];           // 32 KB: this warp's token ids

    const int lane = threadIdx.x & 31;
    const int w    = threadIdx.x >> 5;
    const int b    = blockIdx.x * 2 + w;

    // stage ids into smem (coalesced)
    const int* idp = ids + (long)b * TLEN;
    for (int k = lane; k < TLEN; k += 32) sid[w][k] = idp[k];
    __syncwarp();
    const int* sw = sid[w];

    const int c1 = lane ^ 16;
    const int l2 = lane & 15;

    // 0.5-scaled recurrent kernel columns + biases in registers
    float R1[UNITS], R2[UNITS];
#pragma unroll
    for (int i = 0; i < UNITS; i++) {
        R1[i] = 0.5f * reck[i * GATE3 + c1];
        R2[i] = 0.5f * reck[i * GATE3 + 32 + l2];
    }
    const float b1 = 0.5f * bias[GATE3 + c1];
    const float b2 = 0.5f * bias[GATE3 + 32 + l2];

    float hv[UNITS];
#pragma unroll
    for (int i = 0; i < UNITS; i++) hv[i] = 0.0f;
    float hcur = 0.0f;                      // lane u (<16) holds h[u]

    const float* mytab = g_table2 + 2 * lane;

    // prefetch ring: one LDG.64 per step gives both x-values (pre-scaled)
    float2 xb[PD];
#pragma unroll
    for (int k = 0; k < PD; k++)
        xb[k] = *reinterpret_cast<const float2*>(mytab + ((long)sw[k] << 6));

    for (int t0 = 0; t0 < TLEN; t0 += PD) {
#pragma unroll
        for (int k = 0; k < PD; k++) {
            const float x1 = xb[k].x;       // 0.5*xproj[c1]
            const float x2 = xb[k].y;       // 0.5*xproj[32+l2]

            // refill ring PD steps ahead (wrap mask avoids ISETP/SEL;
            // wrapped loads are never consumed)
            int idn = sw[(t0 + k + PD) & (TLEN - 1)];
            xb[k] = *reinterpret_cast<const float2*>(mytab + ((long)idn << 6));

            const float bx = b1 + x1;

            // broadcast-consumption order aligned: shuffles were issued in
            // index order last step; chains consume hv[j] innermost first.
            float p0 = fmaf(hv[12], R1[12], fmaf(hv[8],  R1[8],
                       fmaf(hv[4],  R1[4],  fmaf(hv[0],  R1[0],  bx))));
            float p1 = fmaf(hv[13], R1[13], fmaf(hv[9],  R1[9],
                       fmaf(hv[5],  R1[5],  hv[1]  * R1[1])));
            float p2 = fmaf(hv[14], R1[14], fmaf(hv[10], R1[10],
                       fmaf(hv[6],  R1[6],  hv[2]  * R1[2])));
            float p3 = fmaf(hv[15], R1[15], fmaf(hv[11], R1[11],
                       fmaf(hv[7],  R1[7],  hv[3]  * R1[3])));
            float acc1 = (p0 + p1) + (p2 + p3);     // 0.5*(x1 + h@R1 + b1)

            float q0 = fmaf(hv[12], R2[12], fmaf(hv[8],  R2[8],
                       fmaf(hv[4],  R2[4],  fmaf(hv[0],  R2[0],  b2))));
            float q1 = fmaf(hv[13], R2[13], fmaf(hv[9],  R2[9],
                       fmaf(hv[5],  R2[5],  hv[1]  * R2[1])));
            float q2 = fmaf(hv[14], R2[14], fmaf(hv[10], R2[10],
                       fmaf(hv[6],  R2[6],  hv[2]  * R2[2])));
            float q3 = fmaf(hv[15], R2[15], fmaf(hv[11], R2[11],
                       fmaf(hv[7],  R2[7],  hv[3]  * R2[3])));
            float acc2 = (q0 + q1) + (q2 + q3);     // 0.5*(h@R2 + b2) = 0.5*rh

            // shared gate: lanes<16 -> r, lanes>=16 -> z  (exact sigmoid via tanh)
            float g1 = fmaf(0.5f, tanh_ap(acc1), 0.5f);
            // pull z down from lane u+16; overlaps the candidate activation
            float z  = __shfl_down_sync(0xffffffffu, g1, 16);

            // candidate: y = 0.5*(xh + r*rh); hh = sigmoid(2y) via ex2+rcp
            float y  = fmaf(g1, acc2, x2);
            float e  = ex2_ap(y * -2.8853900817779268f);   // exp(-(xh + r*rh))
            float hh = rcp_ap(1.0f + e);

            float hn = fmaf(z, hcur - hh, hh);
            hcur = hn;

            // broadcast new state; emission order matches chain consumption
#pragma unroll
            for (int i = 0; i < UNITS; i++)
                hv[i] = __shfl_sync(0xffffffffu, hn, i);
        }
    }

    if (lane < 16) out[(long)b * UNITS + lane] = hcur;
}

// ---------------------------------------------------------------------------
extern "C" void kernel_launch(void* const* d_in, const int* in_sizes, int n_in,
                              void* d_out, int out_size)
{
    const int*   ids  = (const int*)  d_in[0];   // [256, 4096] int32
    const float* emb  = (const float*)d_in[1];   // [50001, 32]
    const float* kern = (const float*)d_in[2];   // [32, 48]
    const float* reck = (const float*)d_in[3];   // [16, 48]
    const float* bias = (const float*)d_in[4];   // [2, 48]
    float*       out  = (float*)d_out;           // [256, 16]

    (void)in_sizes; (void)n_in; (void)out_size;

    build_table<<<256, 128>>>(emb, kern, bias);
    gru_scan<<<BATCH / 2, 64>>>(ids, reck, bias, out);
}

// round 13
// speedup vs baseline: 1.2697x; 1.1095x over previous
#include <cuda_runtime.h>

#define NVOCAB 50001   // VOCAB + 1 rows
#define EMB    32
#define UNITS  16
#define BATCH  256
#define TLEN   4096
#define GATE3  48
#define PD     8       // prefetch depth (steps)

// Repacked, pre-scaled input projection table: [NVOCAB][64] floats.
// For lane l (l2 = l&15, c1 = l^16):
//   pos 2l   = 0.5 * (emb@kernel + bias0)[c1]       (r-col for l<16, z-col for l>=16)
//   pos 2l+1 = 0.5 * (emb@kernel + bias0)[32 + l2]  (candidate col)
__device__ float g_table2[(long)NVOCAB * 64];

__device__ __forceinline__ float tanh_ap(float x) {
    float y; asm("tanh.approx.f32 %0, %1;" : "=f"(y) : "f"(x)); return y;
}
__device__ __forceinline__ unsigned long long fma2(unsigned long long a,
                                                   unsigned long long b,
                                                   unsigned long long c) {
    unsigned long long d;
    asm("fma.rn.f32x2 %0, %1, %2, %3;" : "=l"(d) : "l"(a), "l"(b), "l"(c));
    return d;
}
__device__ __forceinline__ unsigned long long mul2(unsigned long long a,
                                                   unsigned long long b) {
    unsigned long long d;
    asm("mul.rn.f32x2 %0, %1, %2;" : "=l"(d) : "l"(a), "l"(b));
    return d;
}
__device__ __forceinline__ unsigned long long add2(unsigned long long a,
                                                   unsigned long long b) {
    unsigned long long d;
    asm("add.rn.f32x2 %0, %1, %2;" : "=l"(d) : "l"(a), "l"(b));
    return d;
}
__device__ __forceinline__ unsigned long long packf2(float lo, float hi) {
    unsigned long long d;
    asm("mov.b64 %0, {%1, %2};" : "=l"(d) : "f"(lo), "f"(hi));
    return d;
}
__device__ __forceinline__ void unpackf2(unsigned long long v, float& lo, float& hi) {
    asm("mov.b64 {%0, %1}, %2;" : "=f"(lo), "=f"(hi) : "l"(v));
}
__device__ __forceinline__ void lds_v2u64(unsigned int addr,
                                          unsigned long long& a,
                                          unsigned long long& b) {
    asm volatile("ld.shared.v2.b64 {%0, %1}, [%2];" : "=l"(a), "=l"(b) : "r"(addr));
}
__device__ __forceinline__ void sts_u64(unsigned int addr, unsigned long long v) {
    asm volatile("st.shared.b64 [%0], %1;" :: "r"(addr), "l"(v) : "memory");
}
__device__ __forceinline__ unsigned int smem_u32(const void* p) {
    unsigned int a;
    asm("{ .reg .u64 t; cvta.to.shared.u64 t, %1; cvt.u32.u64 %0, t; }"
        : "=r"(a) : "l"(p));
    return a;
}

// ---------------------------------------------------------------------------
// Kernel A: build the repacked table.  One warp per vocab row (strided).
// ---------------------------------------------------------------------------
__global__ __launch_bounds__(128) void build_table(
    const float* __restrict__ emb,
    const float* __restrict__ kern,
    const float* __restrict__ bias)
{
    const int lane = threadIdx.x & 31;
    const int l2   = lane & 15;
    const int c1   = lane ^ 16;
    const int w    = (blockIdx.x * blockDim.x + threadIdx.x) >> 5;
    const int nw   = (gridDim.x * blockDim.x) >> 5;

    float KA[EMB], KB[EMB];
#pragma unroll
    for (int e = 0; e < EMB; e++) {
        KA[e] = kern[e * GATE3 + c1];
        KB[e] = kern[e * GATE3 + 32 + l2];
    }
    const float bA = bias[c1];
    const float bB = bias[32 + l2];

    for (int v = w; v < NVOCAB; v += nw) {
        float ev = emb[(long)v * EMB + lane];   // coalesced 128B
        float a = bA, b = bB;
#pragma unroll
        for (int e = 0; e < EMB; e++) {
            float s = __shfl_sync(0xffffffffu, ev, e);
            a = fmaf(s, KA[e], a);
            b = fmaf(s, KB[e], b);
        }
        float2 p; p.x = 0.5f * a; p.y = 0.5f * b;
        *reinterpret_cast<float2*>(&g_table2[(long)v * 64 + 2 * lane]) = p;
    }
}

// ---------------------------------------------------------------------------
// Kernel B: GRU scan. One batch per warp; 2 warps per CTA (SMSP 0 and 1).
// Gate order in weights: z (0-15), r (16-31), h (32-47).
// Lane mapping: c1 = l^16 -> lanes 0-15 compute the r-column, lanes 16-31 the
// z-column with the SAME instructions; every lane also carries the candidate
// column 32+l2 in the .y slot of a packed f32x2 accumulator chain.
//
// State broadcast: lanes 0-15 store (hn,hn) as 8B into a per-warp ping-pong
// SMEM buffer; after one __syncwarp all lanes reload 8 duplicated pairs via
// ld.shared.v2.b64 and feed them straight into fma.rn.f32x2 chains.
// Everything pre-scaled by 0.5 so both activations are exact sigmoids via
// MUFU tanh: sig(2y) = 0.5 + 0.5*tanh(y).
// ---------------------------------------------------------------------------
__global__ __launch_bounds__(64, 1) void gru_scan(
    const int*   __restrict__ ids,
    const float* __restrict__ reck,
    const float* __restrict__ bias,
    float*       __restrict__ out)
{
    __shared__ int sid[2][TLEN];                       // 32 KB token ids
    __shared__ unsigned long long hbuf[2][2][UNITS];   // [warp][parity][unit]

    const int lane = threadIdx.x & 31;
    const int w    = threadIdx.x >> 5;
    const int b    = blockIdx.x * 2 + w;

    // stage ids into smem (coalesced)
    const int* idp = ids + (long)b * TLEN;
    for (int k = lane; k < TLEN; k += 32) sid[w][k] = idp[k];

    const int c1 = lane ^ 16;
    const int l2 = lane & 15;

    // packed recurrent columns: RP[i] = 0.5*(reck[i][c1], reck[i][32+l2])
    unsigned long long RP[UNITS];
#pragma unroll
    for (int i = 0; i < UNITS; i++)
        RP[i] = packf2(0.5f * reck[i * GATE3 + c1],
                       0.5f * reck[i * GATE3 + 32 + l2]);
    const float b1 = 0.5f * bias[GATE3 + c1];
    const float b2 = 0.5f * bias[GATE3 + 32 + l2];

    // init h = 0 in parity-0 buffer
    if (lane < UNITS) hbuf[w][0][lane] = 0ull;
    float hcur = 0.0f;                      // lane u (<16) holds h[u]
    __syncwarp();
    const int* sw = sid[w];

    const unsigned int hb0 = smem_u32(&hbuf[w][0][0]);
    const unsigned int hb1 = smem_u32(&hbuf[w][1][0]);
    const unsigned int hw0 = hb0 + l2 * 8;  // this lane's store slot, parity 0
    const unsigned int hw1 = hb1 + l2 * 8;

    const float* mytab = g_table2 + 2 * lane;

    // prefetch ring: one LDG.64 per step gives both x-values (pre-scaled)
    float2 xb[PD];
#pragma unroll
    for (int k = 0; k < PD; k++)
        xb[k] = *reinterpret_cast<const float2*>(mytab + ((long)sw[k] << 6));

    for (int t0 = 0; t0 < TLEN; t0 += PD) {
#pragma unroll
        for (int k = 0; k < PD; k++) {
            const int par = k & 1;          // (t0+k)&1 == k&1 since PD even
            const unsigned int rbase = par ? hb1 : hb0;
            const unsigned int wslot = par ? hw0 : hw1;

            const float x1 = xb[k].x;       // 0.5*xproj[c1]
            const float x2 = xb[k].y;       // 0.5*xproj[32+l2]

            // refill ring PD steps ahead (mask-wrap; wrapped loads unused)
            int idn = sw[(t0 + k + PD) & (TLEN - 1)];
            xb[k] = *reinterpret_cast<const float2*>(mytab + ((long)idn << 6));

            // load duplicated h pairs (broadcast LDS, conflict-free)
            unsigned long long P[UNITS];
#pragma unroll
            for (int i = 0; i < UNITS; i += 2)
                lds_v2u64(rbase + i * 8, P[i], P[i + 1]);

            // packed dual matvec: .x accumulates gate column c1,
            // .y accumulates candidate column 32+l2
            unsigned long long seed = packf2(b1 + x1, b2);
            unsigned long long cA = fma2(P[0],  RP[0],  seed);
            cA = fma2(P[1],  RP[1],  cA);
            cA = fma2(P[2],  RP[2],  cA);
            cA = fma2(P[3],  RP[3],  cA);
            unsigned long long cB = mul2(P[4],  RP[4]);
            cB = fma2(P[5],  RP[5],  cB);
            cB = fma2(P[6],  RP[6],  cB);
            cB = fma2(P[7],  RP[7],  cB);
            unsigned long long cC = mul2(P[8],  RP[8]);
            cC = fma2(P[9],  RP[9],  cC);
            cC = fma2(P[10], RP[10], cC);
            cC = fma2(P[11], RP[11], cC);
            unsigned long long cD = mul2(P[12], RP[12]);
            cD = fma2(P[13], RP[13], cD);
            cD = fma2(P[14], RP[14], cD);
            cD = fma2(P[15], RP[15], cD);
            unsigned long long s = add2(add2(cA, cB), add2(cC, cD));

            float acc1, acc2;               // unpack is register naming only
            unpackf2(s, acc1, acc2);

            // shared gate: lanes<16 -> r, lanes>=16 -> z
            float t1 = tanh_ap(acc1);
            float t1s = __shfl_down_sync(0xffffffffu, t1, 16); // z's tanh
            float g1 = fmaf(0.5f, t1, 0.5f);                   // r (lanes<16)
            // candidate: hh = sig(xh + r*rh) = 0.5 + 0.5*tanh(x2 + g1*acc2)
            float y  = fmaf(g1, acc2, x2);
            float hh = fmaf(0.5f, tanh_ap(y), 0.5f);
            float z  = fmaf(0.5f, t1s, 0.5f);

            float hn = fmaf(z, hcur - hh, hh);
            hcur = hn;

            // publish new state (duplicated pair) to the other parity buffer
            if (lane < UNITS) sts_u64(wslot, packf2(hn, hn));
            __syncwarp();
        }
    }

    if (lane < 16) out[(long)b * UNITS + lane] = hcur;
}

// ---------------------------------------------------------------------------
extern "C" void kernel_launch(void* const* d_in, const int* in_sizes, int n_in,
                              void* d_out, int out_size)
{
    const int*   ids  = (const int*)  d_in[0];   // [256, 4096] int32
    const float* emb  = (const float*)d_in[1];   // [50001, 32]
    const float* kern = (const float*)d_in[2];   // [32, 48]
    const float* reck = (const float*)d_in[3];   // [16, 48]
    const float* bias = (const float*)d_in[4];   // [2, 48]
    float*       out  = (float*)d_out;           // [256, 16]

    (void)in_sizes; (void)n_in; (void)out_size;

    build_table<<<256, 128>>>(emb, kern, bias);
    gru_scan<<<BATCH / 2, 64>>>(ids, reck, bias, out);
}